// round 15
// baseline (speedup 1.0000x reference)
#include <cuda_runtime.h>
#include <cuda_bf16.h>
#include <math.h>
#include <stdint.h>

#define TT 1024
#define DD 768
#define NH 12
#define NB 4
#define MR (NB*TT)
#define VV 50257
#define NL 12

// ------------------------- device scratch ----------------------------------
__device__ float g_x  [MR * DD];
__device__ __nv_bfloat16 g_qkvh[MR*3*DD], g_qkvl[MR*3*DD];
__device__ __nv_bfloat16 g_hhi[MR*DD], g_hlo[MR*DD];
__device__ __nv_bfloat16 g_ahi[MR*DD], g_alo[MR*DD];
__device__ __nv_bfloat16 g_fhi[MR*4*DD], g_flo[MR*4*DD];
__device__ __nv_bfloat16 g_wq_h[NL*3*DD*DD], g_wq_l[NL*3*DD*DD];
__device__ __nv_bfloat16 g_wp_h[NL*DD*DD],   g_wp_l[NL*DD*DD];
__device__ __nv_bfloat16 g_wf_h[NL*4*DD*DD], g_wf_l[NL*4*DD*DD];
__device__ __nv_bfloat16 g_wm_h[NL*DD*4*DD], g_wm_l[NL*DD*4*DD];
__device__ __nv_bfloat16 g_wt_h[(size_t)VV*DD], g_wt_l[(size_t)VV*DD];

// ------------------------- helpers -----------------------------------------
__device__ __forceinline__ uint32_t smem_u32(const void* p){
    uint32_t a; asm("{ .reg .u64 t; cvta.to.shared.u64 t, %1; cvt.u32.u64 %0, t; }":"=r"(a):"l"(p)); return a;
}
__device__ __forceinline__ void cpasync16(uint32_t dst, const void* src, int srcsize){
    asm volatile("cp.async.cg.shared.global [%0], [%1], 16, %2;"
                 :: "r"(dst), "l"(src), "r"(srcsize) : "memory");
}
__device__ __forceinline__ void ldsm4(uint32_t& r0, uint32_t& r1, uint32_t& r2, uint32_t& r3, uint32_t a){
    asm volatile("ldmatrix.sync.aligned.m8n8.x4.shared.b16 {%0,%1,%2,%3}, [%4];"
                 : "=r"(r0),"=r"(r1),"=r"(r2),"=r"(r3) : "r"(a));
}
__device__ __forceinline__ void ldsm4t(uint32_t& r0, uint32_t& r1, uint32_t& r2, uint32_t& r3, uint32_t a){
    asm volatile("ldmatrix.sync.aligned.m8n8.x4.trans.shared.b16 {%0,%1,%2,%3}, [%4];"
                 : "=r"(r0),"=r"(r1),"=r"(r2),"=r"(r3) : "r"(a));
}
__device__ __forceinline__ void mma16816(float* d, const uint32_t* a, uint32_t b0, uint32_t b1){
    asm volatile("mma.sync.aligned.m16n8k16.row.col.f32.bf16.bf16.f32 "
                 "{%0,%1,%2,%3}, {%4,%5,%6,%7}, {%8,%9}, {%0,%1,%2,%3};"
                 : "+f"(d[0]),"+f"(d[1]),"+f"(d[2]),"+f"(d[3])
                 : "r"(a[0]),"r"(a[1]),"r"(a[2]),"r"(a[3]), "r"(b0),"r"(b1));
}
__device__ __forceinline__ float gelu_f(float x){
    const float c = 0.7978845608028654f;
    return 0.5f*x*(1.0f + tanhf(c*(x + 0.044715f*x*x*x)));
}
__device__ __forceinline__ void split_bf16(float v, __nv_bfloat16& hi, __nv_bfloat16& lo){
    hi = __float2bfloat16(v);
    lo = __float2bfloat16(v - __bfloat162float(hi));
}
__device__ __forceinline__ uint32_t packbf2(float a, float b){
    __nv_bfloat162 t; t.x = __float2bfloat16(a); t.y = __float2bfloat16(b);
    return *(uint32_t*)&t;
}
// 128B-line swizzle: 2 rows/line, 8x16B chunks/line, conflict-free for ldmatrix.
__device__ __forceinline__ uint32_t swz(int row, int chunk){
    return (uint32_t)((row>>1)*128 + ((((row&1)<<2) + chunk) ^ ((row>>1)&7))*16);
}

// --------- merged weight conversion: [K,N] fp32 -> [N,K] bf16 hi/lo --------
__global__ void convt_all_kernel(const float* __restrict__ wq, const float* __restrict__ wp,
                                 const float* __restrict__ wf, const float* __restrict__ wm,
                                 __nv_bfloat16* __restrict__ qh, __nv_bfloat16* __restrict__ ql,
                                 __nv_bfloat16* __restrict__ ph, __nv_bfloat16* __restrict__ pl,
                                 __nv_bfloat16* __restrict__ fh, __nv_bfloat16* __restrict__ fl,
                                 __nv_bfloat16* __restrict__ mh, __nv_bfloat16* __restrict__ ml)
{
    __shared__ float tile[32][33];
    int l = blockIdx.y;
    int t = blockIdx.x;
    const float* in; __nv_bfloat16 *oh, *ol; int K, N, ntile, ktile;
    if (t < 1728){
        in = wq + (size_t)l*DD*3*DD; oh = qh + (size_t)l*3*DD*DD; ol = ql + (size_t)l*3*DD*DD;
        K = DD; N = 3*DD; ntile = t % 72; ktile = t / 72;
    } else if ((t -= 1728) < 576){
        in = wp + (size_t)l*DD*DD;   oh = ph + (size_t)l*DD*DD;   ol = pl + (size_t)l*DD*DD;
        K = DD; N = DD; ntile = t % 24; ktile = t / 24;
    } else if ((t -= 576) < 2304){
        in = wf + (size_t)l*DD*4*DD; oh = fh + (size_t)l*4*DD*DD; ol = fl + (size_t)l*4*DD*DD;
        K = DD; N = 4*DD; ntile = t % 96; ktile = t / 96;
    } else {
        t -= 2304;
        in = wm + (size_t)l*4*DD*DD; oh = mh + (size_t)l*DD*4*DD; ol = ml + (size_t)l*DD*4*DD;
        K = 4*DD; N = DD; ntile = t % 24; ktile = t / 24;
    }
    int n0 = ntile*32, k0 = ktile*32, tx = threadIdx.x, ty = threadIdx.y;
    #pragma unroll
    for (int i = 0; i < 32; i += 8)
        tile[ty+i][tx] = in[(size_t)(k0+ty+i)*N + n0+tx];
    __syncthreads();
    #pragma unroll
    for (int i = 0; i < 32; i += 8) {
        __nv_bfloat16 hi, lo; split_bf16(tile[tx][ty+i], hi, lo);
        size_t o = (size_t)(n0+ty+i)*K + k0+tx;
        oh[o] = hi; ol[o] = lo;
    }
}
__global__ void conv_kernel(const float* __restrict__ in, __nv_bfloat16* __restrict__ oh,
                            __nv_bfloat16* __restrict__ ol, long cnt)
{
    long i = (long)blockIdx.x*blockDim.x + threadIdx.x;
    if (i < cnt) { __nv_bfloat16 h,l; split_bf16(in[i],h,l); oh[i]=h; ol[i]=l; }
}

// ------------------------------- embedding ---------------------------------
__global__ void embed_kernel(const int* __restrict__ ids, const float* __restrict__ wte,
                             const float* __restrict__ wpe, float* __restrict__ x)
{
    int r = blockIdx.x, tid = threadIdx.x;
    float4 a = *(const float4*)(wte + (size_t)ids[r]*DD + tid*4);
    float4 p = *(const float4*)(wpe + (size_t)(r&(TT-1))*DD + tid*4);
    float4 o; o.x=a.x+p.x; o.y=a.y+p.y; o.z=a.z+p.z; o.w=a.w+p.w;
    *(float4*)(x + (size_t)r*DD + tid*4) = o;
}

// ------------------------------- layernorm ---------------------------------
__global__ __launch_bounds__(256)
void ln_kernel(const float* __restrict__ in, __nv_bfloat16* __restrict__ oh,
               __nv_bfloat16* __restrict__ ol, const float* __restrict__ g,
               const float* __restrict__ b)
{
    __shared__ float red[8]; __shared__ float bc;
    int r = blockIdx.x, tid = threadIdx.x, lane = tid&31, wid = tid>>5;
    const float* row = in + (size_t)r*DD;
    float v0=row[tid], v1=row[tid+256], v2=row[tid+512];
    float s = v0+v1+v2;
    #pragma unroll
    for (int o=16;o>0;o>>=1) s += __shfl_xor_sync(~0u,s,o);
    if (lane==0) red[wid]=s;
    __syncthreads();
    if (tid==0){ float t=0; for(int i=0;i<8;i++) t+=red[i]; bc=t; }
    __syncthreads();
    float mu = bc*(1.f/768.f);
    float d0=v0-mu,d1=v1-mu,d2=v2-mu;
    float sq = d0*d0+d1*d1+d2*d2;
    #pragma unroll
    for (int o=16;o>0;o>>=1) sq += __shfl_xor_sync(~0u,sq,o);
    __syncthreads();
    if (lane==0) red[wid]=sq;
    __syncthreads();
    if (tid==0){ float t=0; for(int i=0;i<8;i++) t+=red[i]; bc=t; }
    __syncthreads();
    float rs = rsqrtf(bc*(1.f/768.f) + 1e-5f);
    size_t base = (size_t)r*DD;
    #pragma unroll
    for (int i=0;i<3;i++){
        int c = tid + i*256;
        float d = (i==0)?d0:(i==1)?d1:d2;
        __nv_bfloat16 hi,lo; split_bf16(d*rs*g[c]+b[c],hi,lo);
        oh[base+c]=hi; ol[base+c]=lo;
    }
}

// -------------- mma.sync GEMM: C[M,N] = A[M,K] @ B[N,K]^T ------------------
// 3-stage cp.async pipeline, ONE __syncthreads per k-chunk.
// 128B-line swizzled smem (conflict-free ldmatrix, 16B-aligned cp.async).
// EPI: 0 none->f32, 2 +bias,gelu->bf16 hi/lo, 3 +bias+res->f32, 4 +bias->bf16 hi/lo
#define TSTG (128*32)               // bf16 per tile buffer (8192)
#define STAGE (4*TSTG)
#define GSMEM_BYTES (3*STAGE*2)     // 98304

template<int EPI>
__global__ __launch_bounds__(256, 2)
void mmagemm_kernel(const __nv_bfloat16* __restrict__ Ah, const __nv_bfloat16* __restrict__ Al,
                    const __nv_bfloat16* __restrict__ Bh, const __nv_bfloat16* __restrict__ Bl,
                    const float* __restrict__ bias, const float* __restrict__ res,
                    float* __restrict__ Cf, __nv_bfloat16* __restrict__ Chi,
                    __nv_bfloat16* __restrict__ Clo, int M, int N, int K)
{
    extern __shared__ __align__(16) __nv_bfloat16 sm[];
    int tid = threadIdx.x, lane = tid&31, w = tid>>5;
    int wr = w>>2, wc = w&3;
    int m0 = blockIdx.x*128, n0 = blockIdx.y*128;
    uint32_t smb = smem_u32(sm);

    float acc[4][4][4];
    #pragma unroll
    for (int i=0;i<4;i++) for (int j=0;j<4;j++) for (int k=0;k<4;k++) acc[i][j][k]=0.f;

    int ntk = K >> 5;

    auto issue = [&](int c){
        int kk = c << 5;
        uint32_t sb = smb + (uint32_t)((c%3)*STAGE)*2;
        #pragma unroll
        for (int h = 0; h < 2; h++){
            int t = tid + h*256;
            int row = t>>2, seg = t&3;
            uint32_t off = swz(row, seg);                     // 16B-aligned
            size_t ga = (size_t)(m0+row)*K + kk + seg*8;
            cpasync16(sb + off,             Ah + ga, 16);
            cpasync16(sb + TSTG*2 + off,    Al + ga, 16);
            int n = n0 + row;
            size_t gb = (size_t)(n < N ? n : 0)*K + kk + seg*8;
            int bsz = (n < N) ? 16 : 0;
            cpasync16(sb + 2*TSTG*2 + off,  Bh + gb, bsz);
            cpasync16(sb + 3*TSTG*2 + off,  Bl + gb, bsz);
        }
        asm volatile("cp.async.commit_group;" ::: "memory");
    };

    issue(0);
    if (ntk > 1) issue(1);

    for (int c = 0; c < ntk; c++){
        if (c+1 < ntk){
            asm volatile("cp.async.wait_group 1;" ::: "memory");
        } else {
            asm volatile("cp.async.wait_group 0;" ::: "memory");
        }
        __syncthreads();
        if (c+2 < ntk) issue(c+2);   // overwrites stage (c-1)%3: reads proven done

        uint32_t tb = smb + (uint32_t)((c%3)*STAGE)*2;
        #pragma unroll
        for (int ks = 0; ks < 2; ks++){
            int chunk = ks*2 + (lane>>4);                    // logical 16B chunk 0..3
            uint32_t aro[4], bro[2];
            #pragma unroll
            for (int mt = 0; mt < 4; mt++){
                int row = wr*64 + mt*16 + (lane&15);
                aro[mt] = swz(row, chunk);
            }
            #pragma unroll
            for (int np = 0; np < 2; np++){
                int row = wc*32 + np*16 + (lane&15);
                bro[np] = swz(row, chunk);
            }

            uint32_t af[4][4], bb[4][2];
            // phase 1: A-hi, B-hi
            #pragma unroll
            for (int mt = 0; mt < 4; mt++)
                ldsm4(af[mt][0], af[mt][1], af[mt][2], af[mt][3], tb + aro[mt]);
            #pragma unroll
            for (int np = 0; np < 2; np++){
                uint32_t r0,r1,r2,r3;
                ldsm4(r0, r1, r2, r3, tb + 2*TSTG*2 + bro[np]);
                bb[np*2+0][0]=r0; bb[np*2+0][1]=r2;
                bb[np*2+1][0]=r1; bb[np*2+1][1]=r3;
            }
            #pragma unroll
            for (int mt = 0; mt < 4; mt++)
                #pragma unroll
                for (int nt = 0; nt < 4; nt++)
                    mma16816(acc[mt][nt], af[mt], bb[nt][0], bb[nt][1]);
            // phase 2: B-lo (A-hi live)
            {
                uint32_t bl2[4][2];
                #pragma unroll
                for (int np = 0; np < 2; np++){
                    uint32_t r0,r1,r2,r3;
                    ldsm4(r0, r1, r2, r3, tb + 3*TSTG*2 + bro[np]);
                    bl2[np*2+0][0]=r0; bl2[np*2+0][1]=r2;
                    bl2[np*2+1][0]=r1; bl2[np*2+1][1]=r3;
                }
                #pragma unroll
                for (int mt = 0; mt < 4; mt++)
                    #pragma unroll
                    for (int nt = 0; nt < 4; nt++)
                        mma16816(acc[mt][nt], af[mt], bl2[nt][0], bl2[nt][1]);
            }
            // phase 3: A-lo over A-hi (B-hi live)
            #pragma unroll
            for (int mt = 0; mt < 4; mt++)
                ldsm4(af[mt][0], af[mt][1], af[mt][2], af[mt][3], tb + TSTG*2 + aro[mt]);
            #pragma unroll
            for (int mt = 0; mt < 4; mt++)
                #pragma unroll
                for (int nt = 0; nt < 4; nt++)
                    mma16816(acc[mt][nt], af[mt], bb[nt][0], bb[nt][1]);
        }
        __syncthreads();   // readers done before next iter's issue overwrites
    }

    // epilogue: paired stores (n, n+1 contiguous)
    int tr = lane>>2, tc = (lane&3)*2;
    #pragma unroll
    for (int mt = 0; mt < 4; mt++){
        #pragma unroll
        for (int i = 0; i < 2; i++){
            int m = m0 + wr*64 + mt*16 + tr + i*8;
            #pragma unroll
            for (int nt = 0; nt < 4; nt++){
                int n = n0 + wc*32 + nt*8 + tc;
                if (n >= N) continue;
                float v0 = acc[mt][nt][i*2+0];
                float v1 = acc[mt][nt][i*2+1];
                if (EPI != 0){ v0 += bias[n]; v1 += bias[n+1]; }
                size_t idx = (size_t)m*N + n;
                bool pair = (n+1 < N);
                if (EPI == 2 || EPI == 4){
                    float g0 = (EPI == 2) ? gelu_f(v0) : v0;
                    float g1 = (EPI == 2) ? gelu_f(v1) : v1;
                    __nv_bfloat16 h0,l0,h1,l1;
                    split_bf16(g0,h0,l0); split_bf16(g1,h1,l1);
                    if (pair){
                        __nv_bfloat162 ph2; ph2.x=h0; ph2.y=h1;
                        __nv_bfloat162 pl2; pl2.x=l0; pl2.y=l1;
                        *(__nv_bfloat162*)&Chi[idx] = ph2;
                        *(__nv_bfloat162*)&Clo[idx] = pl2;
                    } else { Chi[idx]=h0; Clo[idx]=l0; }
                } else if (EPI == 3){
                    if (pair){
                        float2 r2 = *(const float2*)&res[idx];
                        float2 o2; o2.x = v0 + r2.x; o2.y = v1 + r2.y;
                        *(float2*)&Cf[idx] = o2;
                    } else Cf[idx] = v0 + res[idx];
                } else {
                    Cf[idx] = v0;
                    if (pair) Cf[idx+1] = v1;
                }
            }
        }
    }
}

// --------------------- tensor-core flash attention --------------------------
#define AQPAD 72
#define ATILE (64*AQPAD)
#define AT_BYTES (6*ATILE*2)   // 55296

__global__ __launch_bounds__(128)
void attn_mma_kernel(const __nv_bfloat16* __restrict__ gh, const __nv_bfloat16* __restrict__ gl,
                     __nv_bfloat16* __restrict__ oh, __nv_bfloat16* __restrict__ ol)
{
    extern __shared__ __align__(16) __nv_bfloat16 smA[];
    uint32_t sb = smem_u32(smA);
    uint32_t sQh = sb,              sQl = sb + ATILE*2;
    uint32_t sKh = sb + 2*ATILE*2,  sKl = sb + 3*ATILE*2;
    uint32_t sVh = sb + 4*ATILE*2,  sVl = sb + 5*ATILE*2;
    int qt = blockIdx.x, h = blockIdx.y, b = blockIdx.z;
    int tid = threadIdx.x, lane = tid&31, w = tid>>5;

    for (int i = tid; i < 512; i += 128){
        int r = i>>3, sg = i&7;
        size_t g = ((size_t)(b*TT + qt*64 + r))*(3*DD) + h*64 + sg*8;
        uint32_t off = (uint32_t)(r*AQPAD + sg*8)*2;
        cpasync16(sQh + off, gh + g, 16);
        cpasync16(sQl + off, gl + g, 16);
    }
    asm volatile("cp.async.commit_group;" ::: "memory");
    asm volatile("cp.async.wait_group 0;" ::: "memory");
    __syncthreads();

    uint32_t qfh[4][4], qfl[4][4];
    #pragma unroll
    for (int kk = 0; kk < 4; kk++){
        uint32_t off = (uint32_t)((w*16 + (lane&15))*AQPAD + kk*16 + (lane>>4)*8)*2;
        ldsm4(qfh[kk][0], qfh[kk][1], qfh[kk][2], qfh[kk][3], sQh + off);
        ldsm4(qfl[kk][0], qfl[kk][1], qfl[kk][2], qfl[kk][3], sQl + off);
    }

    float oacc[8][4];
    #pragma unroll
    for (int n=0;n<8;n++) for (int j=0;j<4;j++) oacc[n][j]=0.f;
    float mA=-3.0e38f, mB=-3.0e38f, lA=0.f, lB=0.f;
    int tr = lane>>2, tc = (lane&3)*2;
    int rowA = qt*64 + w*16 + tr, rowB = rowA + 8;

    for (int kt = 0; kt <= qt; kt++){
        __syncthreads();
        for (int i = tid; i < 512; i += 128){
            int r = i>>3, sg = i&7;
            size_t g = ((size_t)(b*TT + kt*64 + r))*(3*DD) + DD + h*64 + sg*8;
            uint32_t off = (uint32_t)(r*AQPAD + sg*8)*2;
            cpasync16(sKh + off, gh + g, 16);
            cpasync16(sKl + off, gl + g, 16);
            cpasync16(sVh + off, gh + g + DD, 16);
            cpasync16(sVl + off, gl + g + DD, 16);
        }
        asm volatile("cp.async.commit_group;" ::: "memory");
        asm volatile("cp.async.wait_group 0;" ::: "memory");
        __syncthreads();

        float sacc[8][4];
        #pragma unroll
        for (int n=0;n<8;n++) for (int j=0;j<4;j++) sacc[n][j]=0.f;
        #pragma unroll
        for (int kk = 0; kk < 4; kk++){
            uint32_t kb[8][2];
            #pragma unroll
            for (int g2 = 0; g2 < 4; g2++){
                uint32_t r0,r1,r2,r3;
                uint32_t off = (uint32_t)((g2*16 + (lane&15))*AQPAD + kk*16 + (lane>>4)*8)*2;
                ldsm4(r0,r1,r2,r3, sKh + off);
                kb[2*g2][0]=r0; kb[2*g2][1]=r2; kb[2*g2+1][0]=r1; kb[2*g2+1][1]=r3;
            }
            #pragma unroll
            for (int n = 0; n < 8; n++) mma16816(sacc[n], qfh[kk], kb[n][0], kb[n][1]);
            #pragma unroll
            for (int n = 0; n < 8; n++) mma16816(sacc[n], qfl[kk], kb[n][0], kb[n][1]);
            #pragma unroll
            for (int g2 = 0; g2 < 4; g2++){
                uint32_t r0,r1,r2,r3;
                uint32_t off = (uint32_t)((g2*16 + (lane&15))*AQPAD + kk*16 + (lane>>4)*8)*2;
                ldsm4(r0,r1,r2,r3, sKl + off);
                kb[2*g2][0]=r0; kb[2*g2][1]=r2; kb[2*g2+1][0]=r1; kb[2*g2+1][1]=r3;
            }
            #pragma unroll
            for (int n = 0; n < 8; n++) mma16816(sacc[n], qfh[kk], kb[n][0], kb[n][1]);
        }
        #pragma unroll
        for (int n = 0; n < 8; n++){
            sacc[n][0]*=0.125f; sacc[n][1]*=0.125f; sacc[n][2]*=0.125f; sacc[n][3]*=0.125f;
        }
        if (kt == qt){
            #pragma unroll
            for (int n = 0; n < 8; n++){
                int col = kt*64 + n*8 + tc;
                if (col   > rowA) sacc[n][0] = -3.0e38f;
                if (col+1 > rowA) sacc[n][1] = -3.0e38f;
                if (col   > rowB) sacc[n][2] = -3.0e38f;
                if (col+1 > rowB) sacc[n][3] = -3.0e38f;
            }
        }
        float tmA=-3.0e38f, tmB=-3.0e38f;
        #pragma unroll
        for (int n = 0; n < 8; n++){
            tmA = fmaxf(tmA, fmaxf(sacc[n][0], sacc[n][1]));
            tmB = fmaxf(tmB, fmaxf(sacc[n][2], sacc[n][3]));
        }
        tmA = fmaxf(tmA, __shfl_xor_sync(~0u, tmA, 1));
        tmA = fmaxf(tmA, __shfl_xor_sync(~0u, tmA, 2));
        tmB = fmaxf(tmB, __shfl_xor_sync(~0u, tmB, 1));
        tmB = fmaxf(tmB, __shfl_xor_sync(~0u, tmB, 2));
        float mnA = fmaxf(mA, tmA), mnB = fmaxf(mB, tmB);
        float cA = __expf(mA - mnA), cB = __expf(mB - mnB);
        lA *= cA; lB *= cB;
        #pragma unroll
        for (int n = 0; n < 8; n++){
            oacc[n][0]*=cA; oacc[n][1]*=cA; oacc[n][2]*=cB; oacc[n][3]*=cB;
        }
        uint32_t ph[4][4], pl[4][4];
        float plA = 0.f, plB = 0.f;
        #pragma unroll
        for (int n = 0; n < 8; n++){
            float e0 = __expf(sacc[n][0]-mnA), e1 = __expf(sacc[n][1]-mnA);
            float e2 = __expf(sacc[n][2]-mnB), e3 = __expf(sacc[n][3]-mnB);
            plA += e0+e1; plB += e2+e3;
            __nv_bfloat16 h0=__float2bfloat16(e0), h1=__float2bfloat16(e1);
            __nv_bfloat16 h2=__float2bfloat16(e2), h3=__float2bfloat16(e3);
            int t2 = n>>1, hf = n&1;
            ph[t2][hf*2+0] = packbf2(__bfloat162float(h0), __bfloat162float(h1));
            ph[t2][hf*2+1] = packbf2(__bfloat162float(h2), __bfloat162float(h3));
            pl[t2][hf*2+0] = packbf2(e0-__bfloat162float(h0), e1-__bfloat162float(h1));
            pl[t2][hf*2+1] = packbf2(e2-__bfloat162float(h2), e3-__bfloat162float(h3));
        }
        plA += __shfl_xor_sync(~0u, plA, 1); plA += __shfl_xor_sync(~0u, plA, 2);
        plB += __shfl_xor_sync(~0u, plB, 1); plB += __shfl_xor_sync(~0u, plB, 2);
        lA += plA; lB += plB;
        #pragma unroll
        for (int kk = 0; kk < 4; kk++){
            uint32_t vb[8][2];
            #pragma unroll
            for (int g2 = 0; g2 < 4; g2++){
                uint32_t r0,r1,r2,r3;
                uint32_t off = (uint32_t)((kk*16 + (lane&15))*AQPAD + g2*16 + (lane>>4)*8)*2;
                ldsm4t(r0,r1,r2,r3, sVh + off);
                vb[2*g2][0]=r0; vb[2*g2][1]=r1; vb[2*g2+1][0]=r2; vb[2*g2+1][1]=r3;
            }
            #pragma unroll
            for (int n = 0; n < 8; n++) mma16816(oacc[n], ph[kk], vb[n][0], vb[n][1]);
            #pragma unroll
            for (int n = 0; n < 8; n++) mma16816(oacc[n], pl[kk], vb[n][0], vb[n][1]);
            #pragma unroll
            for (int g2 = 0; g2 < 4; g2++){
                uint32_t r0,r1,r2,r3;
                uint32_t off = (uint32_t)((kk*16 + (lane&15))*AQPAD + g2*16 + (lane>>4)*8)*2;
                ldsm4t(r0,r1,r2,r3, sVl + off);
                vb[2*g2][0]=r0; vb[2*g2][1]=r1; vb[2*g2+1][0]=r2; vb[2*g2+1][1]=r3;
            }
            #pragma unroll
            for (int n = 0; n < 8; n++) mma16816(oacc[n], ph[kk], vb[n][0], vb[n][1]);
        }
        mA = mnA; mB = mnB;
    }

    float iA = 1.f/lA, iB = 1.f/lB;
    size_t rAo = ((size_t)(b*TT + qt*64 + w*16 + tr))*DD + h*64;
    size_t rBo = rAo + (size_t)8*DD;
    #pragma unroll
    for (int n = 0; n < 8; n++){
        int c = n*8 + tc;
        __nv_bfloat16 hi,lo;
        split_bf16(oacc[n][0]*iA, hi, lo); oh[rAo+c]=hi;   ol[rAo+c]=lo;
        split_bf16(oacc[n][1]*iA, hi, lo); oh[rAo+c+1]=hi; ol[rAo+c+1]=lo;
        split_bf16(oacc[n][2]*iB, hi, lo); oh[rBo+c]=hi;   ol[rBo+c]=lo;
        split_bf16(oacc[n][3]*iB, hi, lo); oh[rBo+c+1]=hi; ol[rBo+c+1]=lo;
    }
}

// ------------------------------- launcher ----------------------------------
extern "C" void kernel_launch(void* const* d_in, const int* in_sizes, int n_in,
                              void* d_out, int out_size)
{
    (void)in_sizes; (void)n_in; (void)out_size;
    const int*   ids    = (const int*)  d_in[0];
    const float* wte    = (const float*)d_in[1];
    const float* wpe    = (const float*)d_in[2];
    const float* ln1g   = (const float*)d_in[3];
    const float* ln1b   = (const float*)d_in[4];
    const float* wattn  = (const float*)d_in[5];
    const float* battn  = (const float*)d_in[6];
    const float* wproj  = (const float*)d_in[7];
    const float* bproj  = (const float*)d_in[8];
    const float* ln2g   = (const float*)d_in[9];
    const float* ln2b   = (const float*)d_in[10];
    const float* wfc    = (const float*)d_in[11];
    const float* bfc    = (const float*)d_in[12];
    const float* wmproj = (const float*)d_in[13];
    const float* bmproj = (const float*)d_in[14];
    const float* lnfg   = (const float*)d_in[15];
    const float* lnfb   = (const float*)d_in[16];
    float* out = (float*)d_out;

    cudaFuncSetAttribute(mmagemm_kernel<0>, cudaFuncAttributeMaxDynamicSharedMemorySize, GSMEM_BYTES);
    cudaFuncSetAttribute(mmagemm_kernel<2>, cudaFuncAttributeMaxDynamicSharedMemorySize, GSMEM_BYTES);
    cudaFuncSetAttribute(mmagemm_kernel<3>, cudaFuncAttributeMaxDynamicSharedMemorySize, GSMEM_BYTES);
    cudaFuncSetAttribute(mmagemm_kernel<4>, cudaFuncAttributeMaxDynamicSharedMemorySize, GSMEM_BYTES);
    cudaFuncSetAttribute(attn_mma_kernel, cudaFuncAttributeMaxDynamicSharedMemorySize, AT_BYTES);

    float *px;
    __nv_bfloat16 *pqh,*pql,*phh,*phl,*pah,*pal,*pfh,*pfl;
    __nv_bfloat16 *wqh,*wql,*wph,*wpl,*wfh,*wfl,*wmh,*wml,*wth,*wtl;
    cudaGetSymbolAddress((void**)&px,   g_x);
    cudaGetSymbolAddress((void**)&pqh,  g_qkvh); cudaGetSymbolAddress((void**)&pql, g_qkvl);
    cudaGetSymbolAddress((void**)&phh,  g_hhi); cudaGetSymbolAddress((void**)&phl, g_hlo);
    cudaGetSymbolAddress((void**)&pah,  g_ahi); cudaGetSymbolAddress((void**)&pal, g_alo);
    cudaGetSymbolAddress((void**)&pfh,  g_fhi); cudaGetSymbolAddress((void**)&pfl, g_flo);
    cudaGetSymbolAddress((void**)&wqh,  g_wq_h); cudaGetSymbolAddress((void**)&wql, g_wq_l);
    cudaGetSymbolAddress((void**)&wph,  g_wp_h); cudaGetSymbolAddress((void**)&wpl, g_wp_l);
    cudaGetSymbolAddress((void**)&wfh,  g_wf_h); cudaGetSymbolAddress((void**)&wfl, g_wf_l);
    cudaGetSymbolAddress((void**)&wmh,  g_wm_h); cudaGetSymbolAddress((void**)&wml, g_wm_l);
    cudaGetSymbolAddress((void**)&wth,  g_wt_h); cudaGetSymbolAddress((void**)&wtl, g_wt_l);

    embed_kernel<<<MR, 192>>>(ids, wte, wpe, px);
    ln_kernel<<<MR, 256>>>(px, phh, phl, ln1g, ln1b);
    convt_all_kernel<<<dim3(6912, NL), dim3(32, 8)>>>(
        wattn, wproj, wfc, wmproj, wqh, wql, wph, wpl, wfh, wfl, wmh, wml);

    for (int l = 0; l < NL; l++){
        if (l > 0)
            ln_kernel<<<MR, 256>>>(px, phh, phl, ln1g + (size_t)l*DD, ln1b + (size_t)l*DD);

        mmagemm_kernel<4><<<dim3(MR/128, 3*DD/128), 256, GSMEM_BYTES>>>(
            phh, phl, wqh + (size_t)l*3*DD*DD, wql + (size_t)l*3*DD*DD,
            battn + (size_t)l*3*DD, nullptr, nullptr, pqh, pql, MR, 3*DD, DD);

        attn_mma_kernel<<<dim3(TT/64, NH, NB), 128, AT_BYTES>>>(pqh, pql, pah, pal);

        mmagemm_kernel<3><<<dim3(MR/128, DD/128), 256, GSMEM_BYTES>>>(
            pah, pal, wph + (size_t)l*DD*DD, wpl + (size_t)l*DD*DD,
            bproj + (size_t)l*DD, px, px, nullptr, nullptr, MR, DD, DD);

        ln_kernel<<<MR, 256>>>(px, phh, phl, ln2g + (size_t)l*DD, ln2b + (size_t)l*DD);

        mmagemm_kernel<2><<<dim3(MR/128, 4*DD/128), 256, GSMEM_BYTES>>>(
            phh, phl, wfh + (size_t)l*4*DD*DD, wfl + (size_t)l*4*DD*DD,
            bfc + (size_t)l*4*DD, nullptr, nullptr, pfh, pfl, MR, 4*DD, DD);

        mmagemm_kernel<3><<<dim3(MR/128, DD/128), 256, GSMEM_BYTES>>>(
            pfh, pfl, wmh + (size_t)l*DD*4*DD, wml + (size_t)l*DD*4*DD,
            bmproj + (size_t)l*DD, px, px, nullptr, nullptr, MR, DD, 4*DD);
    }

    long wcnt = (long)VV*DD;
    conv_kernel<<<(unsigned)((wcnt+255)/256), 256>>>(wte, wth, wtl, wcnt);

    ln_kernel<<<MR, 256>>>(px, phh, phl, lnfg, lnfb);

    mmagemm_kernel<0><<<dim3(MR/128, (VV+127)/128), 256, GSMEM_BYTES>>>(
        phh, phl, wth, wtl, nullptr, nullptr, out, nullptr, nullptr, MR, VV, DD);
}

// round 16
// speedup vs baseline: 1.0863x; 1.0863x over previous
#include <cuda_runtime.h>
#include <cuda_bf16.h>
#include <math.h>
#include <stdint.h>

#define TT 1024
#define DD 768
#define NH 12
#define NB 4
#define MR (NB*TT)
#define VV 50257
#define NL 12

// ------------------------- device scratch ----------------------------------
__device__ float g_x  [MR * DD];
__device__ __nv_bfloat16 g_qkvh[MR*3*DD], g_qkvl[MR*3*DD];
__device__ __nv_bfloat16 g_hhi[MR*DD], g_hlo[MR*DD];
__device__ __nv_bfloat16 g_ahi[MR*DD], g_alo[MR*DD];
__device__ __nv_bfloat16 g_fhi[MR*4*DD], g_flo[MR*4*DD];
__device__ __nv_bfloat16 g_wq_h[NL*3*DD*DD], g_wq_l[NL*3*DD*DD];
__device__ __nv_bfloat16 g_wp_h[NL*DD*DD],   g_wp_l[NL*DD*DD];
__device__ __nv_bfloat16 g_wf_h[NL*4*DD*DD], g_wf_l[NL*4*DD*DD];
__device__ __nv_bfloat16 g_wm_h[NL*DD*4*DD], g_wm_l[NL*DD*4*DD];
__device__ __nv_bfloat16 g_wt_h[(size_t)VV*DD], g_wt_l[(size_t)VV*DD];

// ------------------------- helpers -----------------------------------------
__device__ __forceinline__ uint32_t smem_u32(const void* p){
    uint32_t a; asm("{ .reg .u64 t; cvta.to.shared.u64 t, %1; cvt.u32.u64 %0, t; }":"=r"(a):"l"(p)); return a;
}
__device__ __forceinline__ void cpasync16(uint32_t dst, const void* src, int srcsize){
    asm volatile("cp.async.cg.shared.global [%0], [%1], 16, %2;"
                 :: "r"(dst), "l"(src), "r"(srcsize) : "memory");
}
__device__ __forceinline__ void ldsm4(uint32_t& r0, uint32_t& r1, uint32_t& r2, uint32_t& r3, uint32_t a){
    asm volatile("ldmatrix.sync.aligned.m8n8.x4.shared.b16 {%0,%1,%2,%3}, [%4];"
                 : "=r"(r0),"=r"(r1),"=r"(r2),"=r"(r3) : "r"(a));
}
__device__ __forceinline__ void ldsm4t(uint32_t& r0, uint32_t& r1, uint32_t& r2, uint32_t& r3, uint32_t a){
    asm volatile("ldmatrix.sync.aligned.m8n8.x4.trans.shared.b16 {%0,%1,%2,%3}, [%4];"
                 : "=r"(r0),"=r"(r1),"=r"(r2),"=r"(r3) : "r"(a));
}
__device__ __forceinline__ void mma16816(float* d, const uint32_t* a, uint32_t b0, uint32_t b1){
    asm volatile("mma.sync.aligned.m16n8k16.row.col.f32.bf16.bf16.f32 "
                 "{%0,%1,%2,%3}, {%4,%5,%6,%7}, {%8,%9}, {%0,%1,%2,%3};"
                 : "+f"(d[0]),"+f"(d[1]),"+f"(d[2]),"+f"(d[3])
                 : "r"(a[0]),"r"(a[1]),"r"(a[2]),"r"(a[3]), "r"(b0),"r"(b1));
}
__device__ __forceinline__ float gelu_f(float x){
    const float c = 0.7978845608028654f;
    return 0.5f*x*(1.0f + tanhf(c*(x + 0.044715f*x*x*x)));
}
__device__ __forceinline__ void split_bf16(float v, __nv_bfloat16& hi, __nv_bfloat16& lo){
    hi = __float2bfloat16(v);
    lo = __float2bfloat16(v - __bfloat162float(hi));
}
__device__ __forceinline__ uint32_t packbf2(float a, float b){
    __nv_bfloat162 t; t.x = __float2bfloat16(a); t.y = __float2bfloat16(b);
    return *(uint32_t*)&t;
}
// 128B-line swizzle: 2 rows/line, 8x16B chunks/line, conflict-free for ldmatrix.
__device__ __forceinline__ uint32_t swz(int row, int chunk){
    return (uint32_t)((row>>1)*128 + ((((row&1)<<2) + chunk) ^ ((row>>1)&7))*16);
}

// --------- merged weight conversion: [K,N] fp32 -> [N,K] bf16 hi/lo --------
__global__ void convt_all_kernel(const float* __restrict__ wq, const float* __restrict__ wp,
                                 const float* __restrict__ wf, const float* __restrict__ wm,
                                 __nv_bfloat16* __restrict__ qh, __nv_bfloat16* __restrict__ ql,
                                 __nv_bfloat16* __restrict__ ph, __nv_bfloat16* __restrict__ pl,
                                 __nv_bfloat16* __restrict__ fh, __nv_bfloat16* __restrict__ fl,
                                 __nv_bfloat16* __restrict__ mh, __nv_bfloat16* __restrict__ ml)
{
    __shared__ float tile[32][33];
    int l = blockIdx.y;
    int t = blockIdx.x;
    const float* in; __nv_bfloat16 *oh, *ol; int K, N, ntile, ktile;
    if (t < 1728){
        in = wq + (size_t)l*DD*3*DD; oh = qh + (size_t)l*3*DD*DD; ol = ql + (size_t)l*3*DD*DD;
        K = DD; N = 3*DD; ntile = t % 72; ktile = t / 72;
    } else if ((t -= 1728) < 576){
        in = wp + (size_t)l*DD*DD;   oh = ph + (size_t)l*DD*DD;   ol = pl + (size_t)l*DD*DD;
        K = DD; N = DD; ntile = t % 24; ktile = t / 24;
    } else if ((t -= 576) < 2304){
        in = wf + (size_t)l*DD*4*DD; oh = fh + (size_t)l*4*DD*DD; ol = fl + (size_t)l*4*DD*DD;
        K = DD; N = 4*DD; ntile = t % 96; ktile = t / 96;
    } else {
        t -= 2304;
        in = wm + (size_t)l*4*DD*DD; oh = mh + (size_t)l*DD*4*DD; ol = ml + (size_t)l*DD*4*DD;
        K = 4*DD; N = DD; ntile = t % 24; ktile = t / 24;
    }
    int n0 = ntile*32, k0 = ktile*32, tx = threadIdx.x, ty = threadIdx.y;
    #pragma unroll
    for (int i = 0; i < 32; i += 8)
        tile[ty+i][tx] = in[(size_t)(k0+ty+i)*N + n0+tx];
    __syncthreads();
    #pragma unroll
    for (int i = 0; i < 32; i += 8) {
        __nv_bfloat16 hi, lo; split_bf16(tile[tx][ty+i], hi, lo);
        size_t o = (size_t)(n0+ty+i)*K + k0+tx;
        oh[o] = hi; ol[o] = lo;
    }
}
__global__ void conv_kernel(const float* __restrict__ in, __nv_bfloat16* __restrict__ oh,
                            __nv_bfloat16* __restrict__ ol, long cnt)
{
    long i = (long)blockIdx.x*blockDim.x + threadIdx.x;
    if (i < cnt) { __nv_bfloat16 h,l; split_bf16(in[i],h,l); oh[i]=h; ol[i]=l; }
}

// ------------------------------- embedding ---------------------------------
__global__ void embed_kernel(const int* __restrict__ ids, const float* __restrict__ wte,
                             const float* __restrict__ wpe, float* __restrict__ x)
{
    int r = blockIdx.x, tid = threadIdx.x;
    float4 a = *(const float4*)(wte + (size_t)ids[r]*DD + tid*4);
    float4 p = *(const float4*)(wpe + (size_t)(r&(TT-1))*DD + tid*4);
    float4 o; o.x=a.x+p.x; o.y=a.y+p.y; o.z=a.z+p.z; o.w=a.w+p.w;
    *(float4*)(x + (size_t)r*DD + tid*4) = o;
}

// ------------------------------- layernorm ---------------------------------
__global__ __launch_bounds__(256)
void ln_kernel(const float* __restrict__ in, __nv_bfloat16* __restrict__ oh,
               __nv_bfloat16* __restrict__ ol, const float* __restrict__ g,
               const float* __restrict__ b)
{
    __shared__ float red[8]; __shared__ float bc;
    int r = blockIdx.x, tid = threadIdx.x, lane = tid&31, wid = tid>>5;
    const float* row = in + (size_t)r*DD;
    float v0=row[tid], v1=row[tid+256], v2=row[tid+512];
    float s = v0+v1+v2;
    #pragma unroll
    for (int o=16;o>0;o>>=1) s += __shfl_xor_sync(~0u,s,o);
    if (lane==0) red[wid]=s;
    __syncthreads();
    if (tid==0){ float t=0; for(int i=0;i<8;i++) t+=red[i]; bc=t; }
    __syncthreads();
    float mu = bc*(1.f/768.f);
    float d0=v0-mu,d1=v1-mu,d2=v2-mu;
    float sq = d0*d0+d1*d1+d2*d2;
    #pragma unroll
    for (int o=16;o>0;o>>=1) sq += __shfl_xor_sync(~0u,sq,o);
    __syncthreads();
    if (lane==0) red[wid]=sq;
    __syncthreads();
    if (tid==0){ float t=0; for(int i=0;i<8;i++) t+=red[i]; bc=t; }
    __syncthreads();
    float rs = rsqrtf(bc*(1.f/768.f) + 1e-5f);
    size_t base = (size_t)r*DD;
    #pragma unroll
    for (int i=0;i<3;i++){
        int c = tid + i*256;
        float d = (i==0)?d0:(i==1)?d1:d2;
        __nv_bfloat16 hi,lo; split_bf16(d*rs*g[c]+b[c],hi,lo);
        oh[base+c]=hi; ol[base+c]=lo;
    }
}

// -------------- mma.sync GEMM: C[M,N] = A[M,K] @ B[N,K]^T ------------------
// 3-stage cp.async pipeline, ONE __syncthreads per k-chunk (leading sync of the
// next iteration orders this iteration's reads before the stage is overwritten).
// 128B-line swizzled smem. Template BN in {128, 64}: BN=64 doubles grid.y for
// the N=768 GEMMs (fixes wave quantization: 192 -> 384 CTAs on 296 slots).
// EPI: 0 none->f32, 2 +bias,gelu->bf16 hi/lo, 3 +bias+res->f32, 4 +bias->bf16 hi/lo
#define TSTG (128*32)               // bf16 per tile buffer (8192)
#define STAGE (4*TSTG)
#define GSMEM_BYTES (3*STAGE*2)     // 98304

template<int EPI, int BN>
__global__ __launch_bounds__(256, 2)
void mmagemm_kernel(const __nv_bfloat16* __restrict__ Ah, const __nv_bfloat16* __restrict__ Al,
                    const __nv_bfloat16* __restrict__ Bh, const __nv_bfloat16* __restrict__ Bl,
                    const float* __restrict__ bias, const float* __restrict__ res,
                    float* __restrict__ Cf, __nv_bfloat16* __restrict__ Chi,
                    __nv_bfloat16* __restrict__ Clo, int M, int N, int K)
{
    constexpr int WCN = BN/4;      // n-cols per warp (32 or 16)
    constexpr int NPc = WCN/16;    // B ldsm groups per warp (2 or 1)
    constexpr int NTc = WCN/8;     // n-subtiles per warp (4 or 2)

    extern __shared__ __align__(16) __nv_bfloat16 sm[];
    int tid = threadIdx.x, lane = tid&31, w = tid>>5;
    int wr = w>>2, wc = w&3;
    int m0 = blockIdx.x*128, n0 = blockIdx.y*BN;
    uint32_t smb = smem_u32(sm);

    float acc[4][NTc][4];
    #pragma unroll
    for (int i=0;i<4;i++) for (int j=0;j<NTc;j++) for (int k=0;k<4;k++) acc[i][j][k]=0.f;

    int ntk = K >> 5;

    auto issue = [&](int c){
        int kk = c << 5;
        uint32_t sb = smb + (uint32_t)((c%3)*STAGE)*2;
        #pragma unroll
        for (int h = 0; h < 2; h++){
            int t = tid + h*256;
            int row = t>>2, seg = t&3;
            uint32_t off = swz(row, seg);                     // 16B-aligned
            size_t ga = (size_t)(m0+row)*K + kk + seg*8;
            cpasync16(sb + off,             Ah + ga, 16);
            cpasync16(sb + TSTG*2 + off,    Al + ga, 16);
            if (row < BN){
                int n = n0 + row;
                size_t gb = (size_t)(n < N ? n : 0)*K + kk + seg*8;
                int bsz = (n < N) ? 16 : 0;
                cpasync16(sb + 2*TSTG*2 + off,  Bh + gb, bsz);
                cpasync16(sb + 3*TSTG*2 + off,  Bl + gb, bsz);
            }
        }
        asm volatile("cp.async.commit_group;" ::: "memory");
    };

    issue(0);
    if (ntk > 1) issue(1);

    for (int c = 0; c < ntk; c++){
        if (c+1 < ntk){
            asm volatile("cp.async.wait_group 1;" ::: "memory");
        } else {
            asm volatile("cp.async.wait_group 0;" ::: "memory");
        }
        __syncthreads();             // also orders prev iter's reads vs issue below
        if (c+2 < ntk) issue(c+2);   // overwrites stage (c-1)%3: reads proven done

        uint32_t tb = smb + (uint32_t)((c%3)*STAGE)*2;
        #pragma unroll
        for (int ks = 0; ks < 2; ks++){
            int chunk = ks*2 + (lane>>4);                    // logical 16B chunk 0..3
            uint32_t aro[4], bro[NPc];
            #pragma unroll
            for (int mt = 0; mt < 4; mt++){
                int row = wr*64 + mt*16 + (lane&15);
                aro[mt] = swz(row, chunk);
            }
            #pragma unroll
            for (int np = 0; np < NPc; np++){
                int row = wc*WCN + np*16 + (lane&15);
                bro[np] = swz(row, chunk);
            }

            uint32_t af[4][4], bb[2*NPc][2];
            // phase 1: A-hi, B-hi
            #pragma unroll
            for (int mt = 0; mt < 4; mt++)
                ldsm4(af[mt][0], af[mt][1], af[mt][2], af[mt][3], tb + aro[mt]);
            #pragma unroll
            for (int np = 0; np < NPc; np++){
                uint32_t r0,r1,r2,r3;
                ldsm4(r0, r1, r2, r3, tb + 2*TSTG*2 + bro[np]);
                bb[np*2+0][0]=r0; bb[np*2+0][1]=r2;
                bb[np*2+1][0]=r1; bb[np*2+1][1]=r3;
            }
            #pragma unroll
            for (int mt = 0; mt < 4; mt++)
                #pragma unroll
                for (int nt = 0; nt < NTc; nt++)
                    mma16816(acc[mt][nt], af[mt], bb[nt][0], bb[nt][1]);
            // phase 2: B-lo (A-hi live)
            {
                uint32_t bl2[2*NPc][2];
                #pragma unroll
                for (int np = 0; np < NPc; np++){
                    uint32_t r0,r1,r2,r3;
                    ldsm4(r0, r1, r2, r3, tb + 3*TSTG*2 + bro[np]);
                    bl2[np*2+0][0]=r0; bl2[np*2+0][1]=r2;
                    bl2[np*2+1][0]=r1; bl2[np*2+1][1]=r3;
                }
                #pragma unroll
                for (int mt = 0; mt < 4; mt++)
                    #pragma unroll
                    for (int nt = 0; nt < NTc; nt++)
                        mma16816(acc[mt][nt], af[mt], bl2[nt][0], bl2[nt][1]);
            }
            // phase 3: A-lo over A-hi (B-hi live)
            #pragma unroll
            for (int mt = 0; mt < 4; mt++)
                ldsm4(af[mt][0], af[mt][1], af[mt][2], af[mt][3], tb + TSTG*2 + aro[mt]);
            #pragma unroll
            for (int mt = 0; mt < 4; mt++)
                #pragma unroll
                for (int nt = 0; nt < NTc; nt++)
                    mma16816(acc[mt][nt], af[mt], bb[nt][0], bb[nt][1]);
        }
        // no trailing barrier: next iteration's leading __syncthreads covers it
    }

    // epilogue: paired stores (n, n+1 contiguous)
    int tr = lane>>2, tc = (lane&3)*2;
    #pragma unroll
    for (int mt = 0; mt < 4; mt++){
        #pragma unroll
        for (int i = 0; i < 2; i++){
            int m = m0 + wr*64 + mt*16 + tr + i*8;
            #pragma unroll
            for (int nt = 0; nt < NTc; nt++){
                int n = n0 + wc*WCN + nt*8 + tc;
                if (n >= N) continue;
                float v0 = acc[mt][nt][i*2+0];
                float v1 = acc[mt][nt][i*2+1];
                if (EPI != 0){ v0 += bias[n]; v1 += bias[n+1]; }
                size_t idx = (size_t)m*N + n;
                bool pair = (n+1 < N);
                if (EPI == 2 || EPI == 4){
                    float g0 = (EPI == 2) ? gelu_f(v0) : v0;
                    float g1 = (EPI == 2) ? gelu_f(v1) : v1;
                    __nv_bfloat16 h0,l0,h1,l1;
                    split_bf16(g0,h0,l0); split_bf16(g1,h1,l1);
                    if (pair){
                        __nv_bfloat162 ph2; ph2.x=h0; ph2.y=h1;
                        __nv_bfloat162 pl2; pl2.x=l0; pl2.y=l1;
                        *(__nv_bfloat162*)&Chi[idx] = ph2;
                        *(__nv_bfloat162*)&Clo[idx] = pl2;
                    } else { Chi[idx]=h0; Clo[idx]=l0; }
                } else if (EPI == 3){
                    if (pair){
                        float2 r2 = *(const float2*)&res[idx];
                        float2 o2; o2.x = v0 + r2.x; o2.y = v1 + r2.y;
                        *(float2*)&Cf[idx] = o2;
                    } else Cf[idx] = v0 + res[idx];
                } else {
                    Cf[idx] = v0;
                    if (pair) Cf[idx+1] = v1;
                }
            }
        }
    }
}

// --------------------- tensor-core flash attention --------------------------
#define AQPAD 72
#define ATILE (64*AQPAD)
#define AT_BYTES (6*ATILE*2)   // 55296

__global__ __launch_bounds__(128)
void attn_mma_kernel(const __nv_bfloat16* __restrict__ gh, const __nv_bfloat16* __restrict__ gl,
                     __nv_bfloat16* __restrict__ oh, __nv_bfloat16* __restrict__ ol)
{
    extern __shared__ __align__(16) __nv_bfloat16 smA[];
    uint32_t sb = smem_u32(smA);
    uint32_t sQh = sb,              sQl = sb + ATILE*2;
    uint32_t sKh = sb + 2*ATILE*2,  sKl = sb + 3*ATILE*2;
    uint32_t sVh = sb + 4*ATILE*2,  sVl = sb + 5*ATILE*2;
    int qt = blockIdx.x, h = blockIdx.y, b = blockIdx.z;
    int tid = threadIdx.x, lane = tid&31, w = tid>>5;

    for (int i = tid; i < 512; i += 128){
        int r = i>>3, sg = i&7;
        size_t g = ((size_t)(b*TT + qt*64 + r))*(3*DD) + h*64 + sg*8;
        uint32_t off = (uint32_t)(r*AQPAD + sg*8)*2;
        cpasync16(sQh + off, gh + g, 16);
        cpasync16(sQl + off, gl + g, 16);
    }
    asm volatile("cp.async.commit_group;" ::: "memory");
    asm volatile("cp.async.wait_group 0;" ::: "memory");
    __syncthreads();

    uint32_t qfh[4][4], qfl[4][4];
    #pragma unroll
    for (int kk = 0; kk < 4; kk++){
        uint32_t off = (uint32_t)((w*16 + (lane&15))*AQPAD + kk*16 + (lane>>4)*8)*2;
        ldsm4(qfh[kk][0], qfh[kk][1], qfh[kk][2], qfh[kk][3], sQh + off);
        ldsm4(qfl[kk][0], qfl[kk][1], qfl[kk][2], qfl[kk][3], sQl + off);
    }

    float oacc[8][4];
    #pragma unroll
    for (int n=0;n<8;n++) for (int j=0;j<4;j++) oacc[n][j]=0.f;
    float mA=-3.0e38f, mB=-3.0e38f, lA=0.f, lB=0.f;
    int tr = lane>>2, tc = (lane&3)*2;
    int rowA = qt*64 + w*16 + tr, rowB = rowA + 8;

    for (int kt = 0; kt <= qt; kt++){
        __syncthreads();
        for (int i = tid; i < 512; i += 128){
            int r = i>>3, sg = i&7;
            size_t g = ((size_t)(b*TT + kt*64 + r))*(3*DD) + DD + h*64 + sg*8;
            uint32_t off = (uint32_t)(r*AQPAD + sg*8)*2;
            cpasync16(sKh + off, gh + g, 16);
            cpasync16(sKl + off, gl + g, 16);
            cpasync16(sVh + off, gh + g + DD, 16);
            cpasync16(sVl + off, gl + g + DD, 16);
        }
        asm volatile("cp.async.commit_group;" ::: "memory");
        asm volatile("cp.async.wait_group 0;" ::: "memory");
        __syncthreads();

        float sacc[8][4];
        #pragma unroll
        for (int n=0;n<8;n++) for (int j=0;j<4;j++) sacc[n][j]=0.f;
        #pragma unroll
        for (int kk = 0; kk < 4; kk++){
            uint32_t kb[8][2];
            #pragma unroll
            for (int g2 = 0; g2 < 4; g2++){
                uint32_t r0,r1,r2,r3;
                uint32_t off = (uint32_t)((g2*16 + (lane&15))*AQPAD + kk*16 + (lane>>4)*8)*2;
                ldsm4(r0,r1,r2,r3, sKh + off);
                kb[2*g2][0]=r0; kb[2*g2][1]=r2; kb[2*g2+1][0]=r1; kb[2*g2+1][1]=r3;
            }
            #pragma unroll
            for (int n = 0; n < 8; n++) mma16816(sacc[n], qfh[kk], kb[n][0], kb[n][1]);
            #pragma unroll
            for (int n = 0; n < 8; n++) mma16816(sacc[n], qfl[kk], kb[n][0], kb[n][1]);
            #pragma unroll
            for (int g2 = 0; g2 < 4; g2++){
                uint32_t r0,r1,r2,r3;
                uint32_t off = (uint32_t)((g2*16 + (lane&15))*AQPAD + kk*16 + (lane>>4)*8)*2;
                ldsm4(r0,r1,r2,r3, sKl + off);
                kb[2*g2][0]=r0; kb[2*g2][1]=r2; kb[2*g2+1][0]=r1; kb[2*g2+1][1]=r3;
            }
            #pragma unroll
            for (int n = 0; n < 8; n++) mma16816(sacc[n], qfh[kk], kb[n][0], kb[n][1]);
        }
        #pragma unroll
        for (int n = 0; n < 8; n++){
            sacc[n][0]*=0.125f; sacc[n][1]*=0.125f; sacc[n][2]*=0.125f; sacc[n][3]*=0.125f;
        }
        if (kt == qt){
            #pragma unroll
            for (int n = 0; n < 8; n++){
                int col = kt*64 + n*8 + tc;
                if (col   > rowA) sacc[n][0] = -3.0e38f;
                if (col+1 > rowA) sacc[n][1] = -3.0e38f;
                if (col   > rowB) sacc[n][2] = -3.0e38f;
                if (col+1 > rowB) sacc[n][3] = -3.0e38f;
            }
        }
        float tmA=-3.0e38f, tmB=-3.0e38f;
        #pragma unroll
        for (int n = 0; n < 8; n++){
            tmA = fmaxf(tmA, fmaxf(sacc[n][0], sacc[n][1]));
            tmB = fmaxf(tmB, fmaxf(sacc[n][2], sacc[n][3]));
        }
        tmA = fmaxf(tmA, __shfl_xor_sync(~0u, tmA, 1));
        tmA = fmaxf(tmA, __shfl_xor_sync(~0u, tmA, 2));
        tmB = fmaxf(tmB, __shfl_xor_sync(~0u, tmB, 1));
        tmB = fmaxf(tmB, __shfl_xor_sync(~0u, tmB, 2));
        float mnA = fmaxf(mA, tmA), mnB = fmaxf(mB, tmB);
        float cA = __expf(mA - mnA), cB = __expf(mB - mnB);
        lA *= cA; lB *= cB;
        #pragma unroll
        for (int n = 0; n < 8; n++){
            oacc[n][0]*=cA; oacc[n][1]*=cA; oacc[n][2]*=cB; oacc[n][3]*=cB;
        }
        uint32_t ph[4][4], pl[4][4];
        float plA = 0.f, plB = 0.f;
        #pragma unroll
        for (int n = 0; n < 8; n++){
            float e0 = __expf(sacc[n][0]-mnA), e1 = __expf(sacc[n][1]-mnA);
            float e2 = __expf(sacc[n][2]-mnB), e3 = __expf(sacc[n][3]-mnB);
            plA += e0+e1; plB += e2+e3;
            __nv_bfloat16 h0=__float2bfloat16(e0), h1=__float2bfloat16(e1);
            __nv_bfloat16 h2=__float2bfloat16(e2), h3=__float2bfloat16(e3);
            int t2 = n>>1, hf = n&1;
            ph[t2][hf*2+0] = packbf2(__bfloat162float(h0), __bfloat162float(h1));
            ph[t2][hf*2+1] = packbf2(__bfloat162float(h2), __bfloat162float(h3));
            pl[t2][hf*2+0] = packbf2(e0-__bfloat162float(h0), e1-__bfloat162float(h1));
            pl[t2][hf*2+1] = packbf2(e2-__bfloat162float(h2), e3-__bfloat162float(h3));
        }
        plA += __shfl_xor_sync(~0u, plA, 1); plA += __shfl_xor_sync(~0u, plA, 2);
        plB += __shfl_xor_sync(~0u, plB, 1); plB += __shfl_xor_sync(~0u, plB, 2);
        lA += plA; lB += plB;
        #pragma unroll
        for (int kk = 0; kk < 4; kk++){
            uint32_t vb[8][2];
            #pragma unroll
            for (int g2 = 0; g2 < 4; g2++){
                uint32_t r0,r1,r2,r3;
                uint32_t off = (uint32_t)((kk*16 + (lane&15))*AQPAD + g2*16 + (lane>>4)*8)*2;
                ldsm4t(r0,r1,r2,r3, sVh + off);
                vb[2*g2][0]=r0; vb[2*g2][1]=r1; vb[2*g2+1][0]=r2; vb[2*g2+1][1]=r3;
            }
            #pragma unroll
            for (int n = 0; n < 8; n++) mma16816(oacc[n], ph[kk], vb[n][0], vb[n][1]);
            #pragma unroll
            for (int n = 0; n < 8; n++) mma16816(oacc[n], pl[kk], vb[n][0], vb[n][1]);
            #pragma unroll
            for (int g2 = 0; g2 < 4; g2++){
                uint32_t r0,r1,r2,r3;
                uint32_t off = (uint32_t)((kk*16 + (lane&15))*AQPAD + g2*16 + (lane>>4)*8)*2;
                ldsm4t(r0,r1,r2,r3, sVl + off);
                vb[2*g2][0]=r0; vb[2*g2][1]=r1; vb[2*g2+1][0]=r2; vb[2*g2+1][1]=r3;
            }
            #pragma unroll
            for (int n = 0; n < 8; n++) mma16816(oacc[n], ph[kk], vb[n][0], vb[n][1]);
        }
        mA = mnA; mB = mnB;
    }

    float iA = 1.f/lA, iB = 1.f/lB;
    size_t rAo = ((size_t)(b*TT + qt*64 + w*16 + tr))*DD + h*64;
    size_t rBo = rAo + (size_t)8*DD;
    #pragma unroll
    for (int n = 0; n < 8; n++){
        int c = n*8 + tc;
        __nv_bfloat16 hi,lo;
        split_bf16(oacc[n][0]*iA, hi, lo); oh[rAo+c]=hi;   ol[rAo+c]=lo;
        split_bf16(oacc[n][1]*iA, hi, lo); oh[rAo+c+1]=hi; ol[rAo+c+1]=lo;
        split_bf16(oacc[n][2]*iB, hi, lo); oh[rBo+c]=hi;   ol[rBo+c]=lo;
        split_bf16(oacc[n][3]*iB, hi, lo); oh[rBo+c+1]=hi; ol[rBo+c+1]=lo;
    }
}

// ------------------------------- launcher ----------------------------------
extern "C" void kernel_launch(void* const* d_in, const int* in_sizes, int n_in,
                              void* d_out, int out_size)
{
    (void)in_sizes; (void)n_in; (void)out_size;
    const int*   ids    = (const int*)  d_in[0];
    const float* wte    = (const float*)d_in[1];
    const float* wpe    = (const float*)d_in[2];
    const float* ln1g   = (const float*)d_in[3];
    const float* ln1b   = (const float*)d_in[4];
    const float* wattn  = (const float*)d_in[5];
    const float* battn  = (const float*)d_in[6];
    const float* wproj  = (const float*)d_in[7];
    const float* bproj  = (const float*)d_in[8];
    const float* ln2g   = (const float*)d_in[9];
    const float* ln2b   = (const float*)d_in[10];
    const float* wfc    = (const float*)d_in[11];
    const float* bfc    = (const float*)d_in[12];
    const float* wmproj = (const float*)d_in[13];
    const float* bmproj = (const float*)d_in[14];
    const float* lnfg   = (const float*)d_in[15];
    const float* lnfb   = (const float*)d_in[16];
    float* out = (float*)d_out;

    cudaFuncSetAttribute((const void*)mmagemm_kernel<0,128>, cudaFuncAttributeMaxDynamicSharedMemorySize, GSMEM_BYTES);
    cudaFuncSetAttribute((const void*)mmagemm_kernel<2,128>, cudaFuncAttributeMaxDynamicSharedMemorySize, GSMEM_BYTES);
    cudaFuncSetAttribute((const void*)mmagemm_kernel<3,64>,  cudaFuncAttributeMaxDynamicSharedMemorySize, GSMEM_BYTES);
    cudaFuncSetAttribute((const void*)mmagemm_kernel<4,128>, cudaFuncAttributeMaxDynamicSharedMemorySize, GSMEM_BYTES);
    cudaFuncSetAttribute((const void*)attn_mma_kernel, cudaFuncAttributeMaxDynamicSharedMemorySize, AT_BYTES);

    float *px;
    __nv_bfloat16 *pqh,*pql,*phh,*phl,*pah,*pal,*pfh,*pfl;
    __nv_bfloat16 *wqh,*wql,*wph,*wpl,*wfh,*wfl,*wmh,*wml,*wth,*wtl;
    cudaGetSymbolAddress((void**)&px,   g_x);
    cudaGetSymbolAddress((void**)&pqh,  g_qkvh); cudaGetSymbolAddress((void**)&pql, g_qkvl);
    cudaGetSymbolAddress((void**)&phh,  g_hhi); cudaGetSymbolAddress((void**)&phl, g_hlo);
    cudaGetSymbolAddress((void**)&pah,  g_ahi); cudaGetSymbolAddress((void**)&pal, g_alo);
    cudaGetSymbolAddress((void**)&pfh,  g_fhi); cudaGetSymbolAddress((void**)&pfl, g_flo);
    cudaGetSymbolAddress((void**)&wqh,  g_wq_h); cudaGetSymbolAddress((void**)&wql, g_wq_l);
    cudaGetSymbolAddress((void**)&wph,  g_wp_h); cudaGetSymbolAddress((void**)&wpl, g_wp_l);
    cudaGetSymbolAddress((void**)&wfh,  g_wf_h); cudaGetSymbolAddress((void**)&wfl, g_wf_l);
    cudaGetSymbolAddress((void**)&wmh,  g_wm_h); cudaGetSymbolAddress((void**)&wml, g_wm_l);
    cudaGetSymbolAddress((void**)&wth,  g_wt_h); cudaGetSymbolAddress((void**)&wtl, g_wt_l);

    embed_kernel<<<MR, 192>>>(ids, wte, wpe, px);
    ln_kernel<<<MR, 256>>>(px, phh, phl, ln1g, ln1b);
    convt_all_kernel<<<dim3(6912, NL), dim3(32, 8)>>>(
        wattn, wproj, wfc, wmproj, wqh, wql, wph, wpl, wfh, wfl, wmh, wml);

    for (int l = 0; l < NL; l++){
        if (l > 0)
            ln_kernel<<<MR, 256>>>(px, phh, phl, ln1g + (size_t)l*DD, ln1b + (size_t)l*DD);

        mmagemm_kernel<4,128><<<dim3(MR/128, 3*DD/128), 256, GSMEM_BYTES>>>(
            phh, phl, wqh + (size_t)l*3*DD*DD, wql + (size_t)l*3*DD*DD,
            battn + (size_t)l*3*DD, nullptr, nullptr, pqh, pql, MR, 3*DD, DD);

        attn_mma_kernel<<<dim3(TT/64, NH, NB), 128, AT_BYTES>>>(pqh, pql, pah, pal);

        mmagemm_kernel<3,64><<<dim3(MR/128, DD/64), 256, GSMEM_BYTES>>>(
            pah, pal, wph + (size_t)l*DD*DD, wpl + (size_t)l*DD*DD,
            bproj + (size_t)l*DD, px, px, nullptr, nullptr, MR, DD, DD);

        ln_kernel<<<MR, 256>>>(px, phh, phl, ln2g + (size_t)l*DD, ln2b + (size_t)l*DD);

        mmagemm_kernel<2,128><<<dim3(MR/128, 4*DD/128), 256, GSMEM_BYTES>>>(
            phh, phl, wfh + (size_t)l*4*DD*DD, wfl + (size_t)l*4*DD*DD,
            bfc + (size_t)l*4*DD, nullptr, nullptr, pfh, pfl, MR, 4*DD, DD);

        mmagemm_kernel<3,64><<<dim3(MR/128, DD/64), 256, GSMEM_BYTES>>>(
            pfh, pfl, wmh + (size_t)l*DD*4*DD, wml + (size_t)l*DD*4*DD,
            bmproj + (size_t)l*DD, px, px, nullptr, nullptr, MR, DD, 4*DD);
    }

    long wcnt = (long)VV*DD;
    conv_kernel<<<(unsigned)((wcnt+255)/256), 256>>>(wte, wth, wtl, wcnt);

    ln_kernel<<<MR, 256>>>(px, phh, phl, lnfg, lnfb);

    mmagemm_kernel<0,128><<<dim3(MR/128, (VV+127)/128), 256, GSMEM_BYTES>>>(
        phh, phl, wth, wtl, nullptr, nullptr, out, nullptr, nullptr, MR, VV, DD);
}